// round 2
// baseline (speedup 1.0000x reference)
#include <cuda_runtime.h>
#include <cuda_bf16.h>

// GELU161: out = gelu_tanh(x) * (1 + exp(log_alpha) * tanh(exp(log_sigma) * surp))
// where surp = N / (2*(N-1)) EXACTLY: the double-argsort rank statistic over
// any column is a permutation of {0..N-1}, so mean(2*|rank/(N-1) - 0.5|) is
// data-independent. N = B*T = numel(x)/D, D = 4096.

#define SQRT_2_OVER_PI 0.7978845608028654f
#define GELU_C 0.044715f

__device__ __forceinline__ float tanh_approx(float x) {
    float y;
    asm("tanh.approx.f32 %0, %1;" : "=f"(y) : "f"(x));
    return y;
}

__device__ __forceinline__ float gelu_tanh(float x) {
    float x3 = x * x * x;
    float t = tanh_approx(SQRT_2_OVER_PI * fmaf(GELU_C, x3, x));
    return 0.5f * x * (1.0f + t);
}

__global__ __launch_bounds__(256) void gelu_gate_kernel(
    const float4* __restrict__ x,
    const float* __restrict__ log_alpha,
    const float* __restrict__ log_sigma,
    float4* __restrict__ out,
    int nvec,
    float surp)
{
    int i = blockIdx.x * blockDim.x + threadIdx.x;
    if (i >= nvec) return;

    // Scalar gate: broadcast loads of the two scalar inputs (L2 hit after
    // first touch); ~6 flops against a 32-byte memory transaction.
    float alpha = __expf(__ldg(log_alpha));
    float sigma = __expf(__ldg(log_sigma));
    float gate  = 1.0f + alpha * tanh_approx(sigma * surp);

    float4 v = x[i];
    float4 r;
    r.x = gelu_tanh(v.x) * gate;
    r.y = gelu_tanh(v.y) * gate;
    r.z = gelu_tanh(v.z) * gate;
    r.w = gelu_tanh(v.w) * gate;
    out[i] = r;
}

extern "C" void kernel_launch(void* const* d_in, const int* in_sizes, int n_in,
                              void* d_out, int out_size)
{
    const float* x  = (const float*)d_in[0];
    const float* la = (const float*)d_in[1];
    const float* ls = (const float*)d_in[2];
    float* out = (float*)d_out;

    long long total = (long long)in_sizes[0];
    const long long D = 4096;
    long long N = total / D;                 // B*T tokens
    float surp = (float)((double)N / (2.0 * (double)(N - 1)));

    int nvec = (int)(total / 4);             // 8,388,608 float4s
    int threads = 256;
    int blocks = (nvec + threads - 1) / threads;

    gelu_gate_kernel<<<blocks, threads>>>(
        (const float4*)x, la, ls, (float4*)out, nvec, surp);
}